// round 2
// baseline (speedup 1.0000x reference)
#include <cuda_runtime.h>
#include <math.h>

#define HIDDEN 256
#define NPTS   4096
#define KANCH  64
#define ND     1600            // d-table rows: x in [0, 50)
#define NA     448             // a-table rows: x in [0, 14)
#define RPB    8               // rows per build block
#define INV_H  32.0f           // table rows per unit x

// -ln(10000)/256
#define NEG_LOG1E4_OVER_256 (-0.0359778921f)
// FACTOR_A = 180/(15*pi)
#define FACTOR_A 3.8197186342f

__device__ float  g_WdT[HIDDEN * HIDDEN];
__device__ float  g_WaT[HIDDEN * HIDDEN];
__device__ float2 g_pd[ND * HIDDEN];   // (value, delta-to-next-row), bias folded in
__device__ float2 g_pa[NA * HIDDEN];

// ---------------------------------------------------------------------------
// Transpose Wd, Wa (o-major -> h-major) so the build dot-product is coalesced.
// grid (8,8,2), block (32,8)
// ---------------------------------------------------------------------------
__global__ void transpose_kernel(const float* __restrict__ Wd,
                                 const float* __restrict__ Wa) {
    __shared__ float tile[32][33];
    const float* src = blockIdx.z ? Wa : Wd;
    float*       dst = blockIdx.z ? g_WaT : g_WdT;
    int x = blockIdx.x * 32 + threadIdx.x;
    int y = blockIdx.y * 32 + threadIdx.y;
#pragma unroll
    for (int dy = 0; dy < 32; dy += 8)
        tile[threadIdx.y + dy][threadIdx.x] = src[(y + dy) * HIDDEN + x];
    __syncthreads();
    int xo = blockIdx.y * 32 + threadIdx.x;
    int yo = blockIdx.x * 32 + threadIdx.y;
#pragma unroll
    for (int dy = 0; dy < 32; dy += 8)
        dst[(yo + dy) * HIDDEN + xo] = tile[threadIdx.x][threadIdx.y + dy];
}

// ---------------------------------------------------------------------------
// Build lookup tables: row r of table T holds
//   v[o]  = sum_i sin(x w_i) W[o,2i] + cos(x w_i) W[o,2i+1] + b[o],  x = r/32
//   dv[o] = v_{r+1}[o] - v_r[o]
// One block computes RPB rows (+1 overlap row for the delta).
// grid (ND+NA)/RPB blocks, 256 threads.
// ---------------------------------------------------------------------------
__global__ void build_kernel(const float* __restrict__ bd,
                             const float* __restrict__ ba) {
    __shared__ float emb[RPB + 1][HIDDEN];
    const int b   = blockIdx.x;
    const int tid = threadIdx.x;
    const bool is_a = (b >= ND / RPB);
    const int row0  = is_a ? (b - ND / RPB) * RPB : b * RPB;
    const float* WT   = is_a ? g_WaT : g_WdT;
    const float* bias = is_a ? ba : bd;
    float2* out       = is_a ? g_pa : g_pd;

    // embeddings for RPB+1 consecutive x values
    for (int e = tid; e < (RPB + 1) * 128; e += blockDim.x) {
        int rr = e >> 7;
        int i  = e & 127;
        float x = (float)(row0 + rr) * (1.0f / INV_H);
        float w = expf((float)(2 * i) * NEG_LOG1E4_OVER_256);
        float s, c;
        sincosf(x * w, &s, &c);
        emb[rr][2 * i]     = s;
        emb[rr][2 * i + 1] = c;
    }
    __syncthreads();

    const int o = tid;
    float acc[RPB + 1];
#pragma unroll
    for (int rr = 0; rr <= RPB; rr++) acc[rr] = 0.0f;
    for (int h = 0; h < HIDDEN; h++) {
        float w = __ldg(&WT[h * HIDDEN + o]);
#pragma unroll
        for (int rr = 0; rr <= RPB; rr++)
            acc[rr] = fmaf(emb[rr][h], w, acc[rr]);
    }
    float bo = __ldg(&bias[o]);
#pragma unroll
    for (int rr = 0; rr < RPB; rr++)
        out[(row0 + rr) * HIDDEN + o] = make_float2(acc[rr] + bo, acc[rr + 1] - acc[rr]);
}

// ---------------------------------------------------------------------------
// Main pass: one block per point n, thread o = output channel.
// Phase A (threads 0..63): geometry -> per-k (row offset, frac) for d and a.
// Phase B: 64-way gather + lerp + max, both tables, then sum.
// ---------------------------------------------------------------------------
__global__ void __launch_bounds__(HIDDEN)
main_kernel(const float* __restrict__ points,
            const float* __restrict__ anchors,
            float* __restrict__ out) {
    __shared__ int   s_jd[KANCH];
    __shared__ float s_fd[KANCH];
    __shared__ int   s_ja[KANCH];
    __shared__ float s_fa[KANCH];

    const int n   = blockIdx.x;
    const int tid = threadIdx.x;

    if (tid < KANCH) {
        const float px = __ldg(&points[n * 3 + 0]);
        const float py = __ldg(&points[n * 3 + 1]);
        const float pz = __ldg(&points[n * 3 + 2]);
        const int k  = tid;
        const int k1 = (tid + 1) & (KANCH - 1);
        const float ax = __ldg(&anchors[k * 3 + 0]);
        const float ay = __ldg(&anchors[k * 3 + 1]);
        const float az = __ldg(&anchors[k * 3 + 2]);
        const float bx = __ldg(&anchors[k1 * 3 + 0]);
        const float by = __ldg(&anchors[k1 * 3 + 1]);
        const float bz = __ldg(&anchors[k1 * 3 + 2]);

        float rx = px - ax, ry = py - ay, rz = pz - az;   // ref vector
        float ex = px - bx, ey = py - by, ez = pz - bz;   // next anchor vector

        // d index: dist/SIGMA_D, scaled by 32 rows/unit -> *160
        float dist = sqrtf(rx * rx + ry * ry + rz * rz);
        float td = fminf(dist * 160.0f, 1598.99f);
        int   jd = (int)td;
        s_jd[k] = jd * HIDDEN;
        s_fd[k] = td - (float)jd;

        // angle index
        float cx = ry * ez - rz * ey;
        float cy = rz * ex - rx * ez;
        float cz = rx * ey - ry * ex;
        float sv = sqrtf(cx * cx + cy * cy + cz * cz);
        float cv = rx * ex + ry * ey + rz * ez;
        float ang = atan2f(sv, cv);
        float ta = fminf(ang * (FACTOR_A * 32.0f), 446.99f);
        ta = fmaxf(ta, 0.0f);
        int   ja = (int)ta;
        s_ja[k] = ja * HIDDEN;
        s_fa[k] = ta - (float)ja;
    }
    __syncthreads();

    const int o = tid;
    float accd = -1e30f, acca = -1e30f;
#pragma unroll 8
    for (int k = 0; k < KANCH; k++) {
        float2 vd = __ldg(&g_pd[s_jd[k] + o]);
        float2 va = __ldg(&g_pa[s_ja[k] + o]);
        accd = fmaxf(accd, fmaf(s_fd[k], vd.y, vd.x));
        acca = fmaxf(acca, fmaf(s_fa[k], va.y, va.x));
    }
    out[n * HIDDEN + o] = accd + acca;
}

// ---------------------------------------------------------------------------
extern "C" void kernel_launch(void* const* d_in, const int* in_sizes, int n_in,
                              void* d_out, int out_size) {
    const float* points  = (const float*)d_in[0];
    const float* anchors = (const float*)d_in[1];
    // d_in[2] = cor_score (unused by reference output)
    const float* Wa = (const float*)d_in[3];
    const float* ba = (const float*)d_in[4];
    const float* Wd = (const float*)d_in[5];
    const float* bd = (const float*)d_in[6];
    float* out = (float*)d_out;

    transpose_kernel<<<dim3(8, 8, 2), dim3(32, 8)>>>(Wd, Wa);
    build_kernel<<<(ND + NA) / RPB, HIDDEN>>>(bd, ba);
    main_kernel<<<NPTS, HIDDEN>>>(points, anchors, out);
}

// round 4
// speedup vs baseline: 1.2449x; 1.2449x over previous
#include <cuda_runtime.h>
#include <cuda_fp16.h>
#include <math.h>

#define HIDDEN 256
#define NPTS   4096
#define KANCH  64
#define ND     800             // d-table rows: x in [0, 50), h = 1/16
#define NA     224             // a-table rows: x in [0, 14), h = 1/16
#define RPB    8               // rows per build block
#define INV_H  16.0f           // table rows per unit x

// -ln(10000)/256
#define NEG_LOG1E4_OVER_256 (-0.0359778921f)
// FACTOR_A = 180/(15*pi)
#define FACTOR_A 3.8197186342f

__device__ float g_WdT[HIDDEN * HIDDEN];
__device__ float g_WaT[HIDDEN * HIDDEN];
// Per row r, per channel-pair t (t=0..127):
//   .x = half2( v[2t],  v[2t+1] )   (bias folded in)
//   .y = half2( dv[2t], dv[2t+1] )  (delta to next row)
__device__ uint2 g_pd[ND * (HIDDEN / 2)];
__device__ uint2 g_pa[NA * (HIDDEN / 2)];

__device__ __forceinline__ __half2 as_h2(unsigned int v) {
    __half2 h;
    *reinterpret_cast<unsigned int*>(&h) = v;
    return h;
}
__device__ __forceinline__ unsigned int as_u32(__half2 h) {
    return *reinterpret_cast<unsigned int*>(&h);
}

// ---------------------------------------------------------------------------
// Transpose Wd, Wa (o-major -> h-major) so the build dot-product is coalesced.
// grid (8,8,2), block (32,8)
// ---------------------------------------------------------------------------
__global__ void transpose_kernel(const float* __restrict__ Wd,
                                 const float* __restrict__ Wa) {
    __shared__ float tile[32][33];
    const float* src = blockIdx.z ? Wa : Wd;
    float*       dst = blockIdx.z ? g_WaT : g_WdT;
    int x = blockIdx.x * 32 + threadIdx.x;
    int y = blockIdx.y * 32 + threadIdx.y;
#pragma unroll
    for (int dy = 0; dy < 32; dy += 8)
        tile[threadIdx.y + dy][threadIdx.x] = src[(y + dy) * HIDDEN + x];
    __syncthreads();
    int xo = blockIdx.y * 32 + threadIdx.x;
    int yo = blockIdx.x * 32 + threadIdx.y;
#pragma unroll
    for (int dy = 0; dy < 32; dy += 8)
        dst[(yo + dy) * HIDDEN + xo] = tile[threadIdx.x][threadIdx.y + dy];
}

// ---------------------------------------------------------------------------
// Build half2-packed lookup tables. One block computes RPB rows (+1 overlap
// row for the delta). grid (ND+NA)/RPB blocks, 256 threads.
// ---------------------------------------------------------------------------
__global__ void build_kernel(const float* __restrict__ bd,
                             const float* __restrict__ ba) {
    __shared__ float emb[RPB + 1][HIDDEN];
    __shared__ float accs[RPB + 1][HIDDEN];
    const int b   = blockIdx.x;
    const int tid = threadIdx.x;
    const bool is_a = (b >= ND / RPB);
    const int row0  = is_a ? (b - ND / RPB) * RPB : b * RPB;
    const float* WT   = is_a ? g_WaT : g_WdT;
    const float* bias = is_a ? ba : bd;
    uint2* out        = is_a ? g_pa : g_pd;

    // embeddings for RPB+1 consecutive x values
    for (int e = tid; e < (RPB + 1) * 128; e += blockDim.x) {
        int rr = e >> 7;
        int i  = e & 127;
        float x = (float)(row0 + rr) * (1.0f / INV_H);
        float w = expf((float)(2 * i) * NEG_LOG1E4_OVER_256);
        float s, c;
        sincosf(x * w, &s, &c);
        emb[rr][2 * i]     = s;
        emb[rr][2 * i + 1] = c;
    }
    __syncthreads();

    const int o = tid;
    float acc[RPB + 1];
#pragma unroll
    for (int rr = 0; rr <= RPB; rr++) acc[rr] = 0.0f;
    for (int h = 0; h < HIDDEN; h++) {
        float w = __ldg(&WT[h * HIDDEN + o]);
#pragma unroll
        for (int rr = 0; rr <= RPB; rr++)
            acc[rr] = fmaf(emb[rr][h], w, acc[rr]);
    }
    float bo = __ldg(&bias[o]);
#pragma unroll
    for (int rr = 0; rr <= RPB; rr++) accs[rr][o] = acc[rr] + bo;
    __syncthreads();

    // pack channel pairs into half2 (v, dv)
    if (tid < 128) {
        const int t = tid;
#pragma unroll
        for (int rr = 0; rr < RPB; rr++) {
            float a0 = accs[rr][2 * t],     a1 = accs[rr][2 * t + 1];
            float b0 = accs[rr + 1][2 * t], b1 = accs[rr + 1][2 * t + 1];
            __half2 v  = __floats2half2_rn(a0, a1);
            __half2 dv = __floats2half2_rn(b0 - a0, b1 - a1);
            out[(row0 + rr) * 128 + t] = make_uint2(as_u32(v), as_u32(dv));
        }
    }
}

// ---------------------------------------------------------------------------
// Main pass: one block per point n, 128 threads; thread t handles channels
// (2t, 2t+1) via half2 vector lerp + max.
// ---------------------------------------------------------------------------
__global__ void __launch_bounds__(128)
main_kernel(const float* __restrict__ points,
            const float* __restrict__ anchors,
            float* __restrict__ out) {
    __shared__ uint2 s_idx[KANCH];   // {jd*128, ja*128}
    __shared__ uint2 s_f[KANCH];     // {fd as half2-broadcast, fa as half2-broadcast}

    const int n   = blockIdx.x;
    const int tid = threadIdx.x;

    if (tid < KANCH) {
        const float px = __ldg(&points[n * 3 + 0]);
        const float py = __ldg(&points[n * 3 + 1]);
        const float pz = __ldg(&points[n * 3 + 2]);
        const int k  = tid;
        const int k1 = (tid + 1) & (KANCH - 1);
        const float ax = __ldg(&anchors[k * 3 + 0]);
        const float ay = __ldg(&anchors[k * 3 + 1]);
        const float az = __ldg(&anchors[k * 3 + 2]);
        const float bx = __ldg(&anchors[k1 * 3 + 0]);
        const float by = __ldg(&anchors[k1 * 3 + 1]);
        const float bz = __ldg(&anchors[k1 * 3 + 2]);

        float rx = px - ax, ry = py - ay, rz = pz - az;
        float ex = px - bx, ey = py - by, ez = pz - bz;

        // d index: dist/SIGMA_D * 16 rows/unit -> *80
        float dist = sqrtf(rx * rx + ry * ry + rz * rz);
        float td = fminf(dist * (INV_H / 0.2f), (float)ND - 1.01f);
        int   jd = (int)td;
        float fd = td - (float)jd;

        // angle index: angle * FACTOR_A * 16
        float cx = ry * ez - rz * ey;
        float cy = rz * ex - rx * ez;
        float cz = rx * ey - ry * ex;
        float sv = sqrtf(cx * cx + cy * cy + cz * cz);
        float cv = rx * ex + ry * ey + rz * ez;
        float ang = atan2f(sv, cv);
        float ta = fminf(ang * (FACTOR_A * INV_H), (float)NA - 1.01f);
        ta = fmaxf(ta, 0.0f);
        int   ja = (int)ta;
        float fa = ta - (float)ja;

        s_idx[k] = make_uint2((unsigned)(jd * 128), (unsigned)(ja * 128));
        s_f[k]   = make_uint2(as_u32(__float2half2_rn(fd)),
                              as_u32(__float2half2_rn(fa)));
    }
    __syncthreads();

    __half2 accd = __float2half2_rn(-60000.0f);
    __half2 acca = __float2half2_rn(-60000.0f);

#pragma unroll 8
    for (int k = 0; k < KANCH; k++) {
        uint2 idx = s_idx[k];
        uint2 f   = s_f[k];
        uint2 vd  = __ldg(&g_pd[idx.x + tid]);
        uint2 va  = __ldg(&g_pa[idx.y + tid]);
        accd = __hmax2(accd, __hfma2(as_h2(f.x), as_h2(vd.y), as_h2(vd.x)));
        acca = __hmax2(acca, __hfma2(as_h2(f.y), as_h2(va.y), as_h2(va.x)));
    }

    float2 r;
    r.x = __low2float(accd)  + __low2float(acca);
    r.y = __high2float(accd) + __high2float(acca);
    reinterpret_cast<float2*>(out)[n * 128 + tid] = r;
}

// ---------------------------------------------------------------------------
extern "C" void kernel_launch(void* const* d_in, const int* in_sizes, int n_in,
                              void* d_out, int out_size) {
    const float* points  = (const float*)d_in[0];
    const float* anchors = (const float*)d_in[1];
    // d_in[2] = cor_score (unused by reference output)
    const float* Wa = (const float*)d_in[3];
    const float* ba = (const float*)d_in[4];
    const float* Wd = (const float*)d_in[5];
    const float* bd = (const float*)d_in[6];
    float* out = (float*)d_out;

    transpose_kernel<<<dim3(8, 8, 2), dim3(32, 8)>>>(Wd, Wa);
    build_kernel<<<(ND + NA) / RPB, HIDDEN>>>(bd, ba);
    main_kernel<<<NPTS, 128>>>(points, anchors, out);
}